// round 13
// baseline (speedup 1.0000x reference)
#include <cuda_runtime.h>

#define B_   1024
#define T_   1024
#define HH   64
#define NBR  7
#define NTH  1024
#define NBLK 147        // 147*7 = 1029 >= 1024

// ---- shared memory layout (float offsets) ----
#define OFF_WHEAD 0         // 50*68 = 3400 (+408 slack, read-only overrun ok)
#define OFF_WENC  3808      // 64*28 = 1792 -> 5600 (row-major, k padded to 28)
#define OFF_IN    5600      // 7*24  = 168  -> 5768
#define OFF_XH    5792      // 7*160 = 1120 -> 6912 ; 5792 % 32 == 0
#define OFF_C     6912      // 448 -> 7360
#define OFF_GATE  7360      // 7*256 = 1792 -> 9152
#define SM_TOT    9152      // 36608 bytes

// x j at chunk j>>5 (0,1); h j at chunk 2+(j>>5): row = nb*160, chunk c at c*40
#define XADDR(nb,j) (OFF_XH + (nb)*160 +      ((j)>>5)*40 + ((j)&31))
#define HADDR(nb,j) (OFF_XH + (nb)*160 + 80 + ((j)>>5)*40 + ((j)&31))

#define OFFZ ((size_t)B_ * T_ * 18)
#define OFFH ((size_t)B_ * T_ * 50)
#define OFFC (OFFH + (size_t)B_ * HH)

__device__ __forceinline__ float sigm(float x) {
    return 1.0f / (1.0f + __expf(-x));
}

__global__ __launch_bounds__(NTH, 1)
void wm_lstm_kernel(const float* __restrict__ obs, const float* __restrict__ act,
                    const float* __restrict__ h0,  const float* __restrict__ c0,
                    const float* __restrict__ Wenc, const float* __restrict__ benc,
                    const float* __restrict__ Wih,  const float* __restrict__ Whh,
                    const float* __restrict__ bih,  const float* __restrict__ bhh,
                    const float* __restrict__ Wpred, const float* __restrict__ bpred,
                    const float* __restrict__ Wz,    const float* __restrict__ bz,
                    float* __restrict__ out) {
    __shared__ float sm[SM_TOT];

    const int tid   = threadIdx.x;
    const int bBase = blockIdx.x * NBR;

    // ---- stage shared data ----
    for (int idx = tid; idx < 50 * 64; idx += NTH) {
        int o = idx >> 6, k = idx & 63;
        sm[OFF_WHEAD + o * 68 + k] = (o < 18) ? Wpred[o * 64 + k] : Wz[(o - 18) * 64 + k];
    }
    for (int idx = tid; idx < 64 * 28; idx += NTH) {
        int j = idx / 28, k = idx - j * 28;
        sm[OFF_WENC + idx] = (k < 23) ? Wenc[j * 23 + k] : 0.f;   // row-major, zero-pad
    }
    if (tid < NBR * 24) sm[OFF_IN + tid] = 0.f;                    // incl. pad word 23
    if (tid < NBR * 64) {
        int nb = tid >> 6, j = tid & 63;
        int b = bBase + nb;
        float hv = 0.f, cv = 0.f;
        if (b < B_) { hv = h0[(size_t)b * HH + j]; cv = c0[(size_t)b * HH + j]; }
        sm[HADDR(nb, j)] = hv;
        sm[OFF_C + nb * 64 + j] = cv;
    }

    // ---- gate setup: thread = (gate g, quarter q of concat [x;h]) ----
    const int g = tid >> 2;             // 0..255
    const int q = tid & 3;              // q0,1 -> x halves ; q2,3 -> h halves
    float4 wreg[8];                     // 32 weight floats
    {
        const float* wsrc = (q < 2 ? Wih : Whh) + g * 64 + (q & 1) * 32;
#pragma unroll
        for (int k4 = 0; k4 < 8; k4++)
            wreg[k4] = *(const float4*)(wsrc + k4 * 4);
    }
    const float bg = bih[g] + bhh[g];   // used only by q==0
    const float* vbase = sm + OFF_XH + q * 40;

    // ---- encoder constant ----
    const float be = (tid < NBR * 64) ? benc[tid & 63] : 0.f;

    // ---- input prefetch: 7*23 = 161 scalars per step ----
    const int  pNb = tid / 23;
    const int  pK  = tid - pNb * 23;
    const int  pb  = bBase + pNb;
    const bool pValid = (tid < NBR * 23) && (pb < B_);
    const float* pPtr = nullptr;
    int pStep = 0;
    if (pValid) {
        if (pK < 18) { pPtr = obs + ((size_t)pb * T_) * 18 + pK;       pStep = 18; }
        else         { pPtr = act + ((size_t)pb * T_) * 5 + (pK - 18); pStep = 5;  }
    }
    float rIn = pValid ? pPtr[0] : 0.f;
    // commit t=0 inputs
    if (tid < NBR * 23) sm[OFF_IN + pNb * 24 + pK] = rIn;

    // ---- head setup: thread = (o 0..55, k-chunk 0..3); 224 = 7 full warps ----
    const bool headAct = (tid < 224);
    const int  ho = tid >> 2;           // 0..55 (50..55 = padding lanes)
    const int  hc = tid & 3;
    const float bh = (ho < 18) ? bpred[ho] : ((ho < 50) ? bz[ho - 18] : 0.f);

    __syncthreads();

    for (int t = 0; t < T_; t++) {
        // B: encoder (vectorized) + prefetch next input
        if (pValid && (t + 1 < T_)) rIn = __ldg(pPtr + (size_t)(t + 1) * pStep);
        if (tid < NBR * 64) {
            int nb = tid >> 6, j = tid & 63;
            const float4* wj = (const float4*)(sm + OFF_WENC + j * 28);
            const float4* in = (const float4*)(sm + OFF_IN + nb * 24);
            float a0 = be, a1 = 0.f;
#pragma unroll
            for (int k2 = 0; k2 < 3; k2++) {
                const float4 w0 = wj[2 * k2],     i0 = in[2 * k2];
                const float4 w1 = wj[2 * k2 + 1], i1 = in[2 * k2 + 1];
                a0 = fmaf(w0.x, i0.x, a0); a0 = fmaf(w0.y, i0.y, a0);
                a0 = fmaf(w0.z, i0.z, a0); a0 = fmaf(w0.w, i0.w, a0);
                a1 = fmaf(w1.x, i1.x, a1); a1 = fmaf(w1.y, i1.y, a1);
                a1 = fmaf(w1.z, i1.z, a1); a1 = fmaf(w1.w, i1.w, a1);
            }
            sm[XADDR(nb, j)] = fmaxf(a0 + a1, 0.f);
        }
        __syncthreads();

        // C: gate GEMM — quarter-split, 32 weight regs, 2-level shfl reduce
#pragma unroll
        for (int nb = 0; nb < NBR; nb++) {
            const float4* vp = (const float4*)(vbase + nb * 160);
            float a0 = 0.f, a1 = 0.f;
#pragma unroll
            for (int k2 = 0; k2 < 4; k2++) {
                const float4 w0 = wreg[2 * k2],     v0 = vp[2 * k2];
                const float4 w1 = wreg[2 * k2 + 1], v1 = vp[2 * k2 + 1];
                a0 = fmaf(w0.x, v0.x, a0); a0 = fmaf(w0.y, v0.y, a0);
                a0 = fmaf(w0.z, v0.z, a0); a0 = fmaf(w0.w, v0.w, a0);
                a1 = fmaf(w1.x, v1.x, a1); a1 = fmaf(w1.y, v1.y, a1);
                a1 = fmaf(w1.z, v1.z, a1); a1 = fmaf(w1.w, v1.w, a1);
            }
            float s = a0 + a1;
            s += __shfl_xor_sync(0xffffffffu, s, 1);
            s += __shfl_xor_sync(0xffffffffu, s, 2);
            if (q == 0) sm[OFF_GATE + nb * 256 + g] = s + bg;
        }
        __syncthreads();

        // D: LSTM cell elementwise
        if (tid < NBR * 64) {
            int nb = tid >> 6, j = tid & 63;
            const float* gr = sm + OFF_GATE + nb * 256;
            float gi = gr[j], gf = gr[64 + j], gg = gr[128 + j], go = gr[192 + j];
            float cc = sm[OFF_C + nb * 64 + j];
            cc = sigm(gf) * cc + sigm(gi) * tanhf(gg);
            float hh = sigm(go) * tanhf(cc);
            sm[OFF_C + nb * 64 + j] = cc;
            sm[HADDR(nb, j)] = hh;
        }
        __syncthreads();

        // E: heads (weights loaded once per step, reused over all nb) + commit input
        if (headAct) {
            const float4* wp = (const float4*)(sm + OFF_WHEAD + ho * 68 + hc * 16);
            const float4 w0 = wp[0], w1 = wp[1], w2 = wp[2], w3 = wp[3];
#pragma unroll
            for (int nb = 0; nb < NBR; nb++) {
                const float4* hp = (const float4*)
                    (sm + OFF_XH + nb * 160 + 80 + (hc >> 1) * 40 + (hc & 1) * 16);
                const float4 h0v = hp[0], h1v = hp[1], h2v = hp[2], h3v = hp[3];
                float a0, a1;
                a0 = w0.x * h0v.x;          a1 = w1.x * h1v.x;
                a0 = fmaf(w0.y, h0v.y, a0); a1 = fmaf(w1.y, h1v.y, a1);
                a0 = fmaf(w0.z, h0v.z, a0); a1 = fmaf(w1.z, h1v.z, a1);
                a0 = fmaf(w0.w, h0v.w, a0); a1 = fmaf(w1.w, h1v.w, a1);
                a0 = fmaf(w2.x, h2v.x, a0); a1 = fmaf(w3.x, h3v.x, a1);
                a0 = fmaf(w2.y, h2v.y, a0); a1 = fmaf(w3.y, h3v.y, a1);
                a0 = fmaf(w2.z, h2v.z, a0); a1 = fmaf(w3.z, h3v.z, a1);
                a0 = fmaf(w2.w, h2v.w, a0); a1 = fmaf(w3.w, h3v.w, a1);
                float s = a0 + a1;
                s += __shfl_xor_sync(0xffffffffu, s, 1);
                s += __shfl_xor_sync(0xffffffffu, s, 2);
                int b = bBase + nb;
                if (hc == 0 && ho < 50 && b < B_) {
                    float v = s + bh;
                    size_t row = (size_t)b * T_ + t;
                    if (ho < 18) out[row * 18 + ho] = sigm(v);
                    else         out[OFFZ + row * 32 + (ho - 18)] = v;
                }
            }
        }
        if (tid < NBR * 23) sm[OFF_IN + pNb * 24 + pK] = rIn;   // t+1 inputs
        __syncthreads();
        // loop-top: B reads sIn (committed), C/E read sH written 2 barriers ago
    }

    // final hT / cT
    if (tid < NBR * 64) {
        int nb = tid >> 6, j = tid & 63;
        int b = bBase + nb;
        if (b < B_) {
            out[OFFH + (size_t)b * HH + j] = sm[HADDR(nb, j)];
            out[OFFC + (size_t)b * HH + j] = sm[OFF_C + nb * 64 + j];
        }
    }
}

extern "C" void kernel_launch(void* const* d_in, const int* in_sizes, int n_in,
                              void* d_out, int out_size) {
    (void)in_sizes; (void)n_in; (void)out_size;
    wm_lstm_kernel<<<NBLK, NTH>>>(
        (const float*)d_in[0],  (const float*)d_in[1],
        (const float*)d_in[2],  (const float*)d_in[3],
        (const float*)d_in[4],  (const float*)d_in[5],
        (const float*)d_in[6],  (const float*)d_in[7],
        (const float*)d_in[8],  (const float*)d_in[9],
        (const float*)d_in[10], (const float*)d_in[11],
        (const float*)d_in[12], (const float*)d_in[13],
        (float*)d_out);
}

// round 14
// speedup vs baseline: 1.7502x; 1.7502x over previous
#include <cuda_runtime.h>

#define B_   1024
#define T_   1024
#define NBR  7
#define NTH  512
#define NBLK 147        // 147*7 = 1029 >= 1024

// ---- shared memory layout (float offsets) ----
#define OFF_WENCT 0         // 23*64 = 1472  [k][j] k-major
#define OFF_IN    1472      // 2 buffers * 7*24 = 336 -> 1808
#define OFF_X     1824      // 448 -> 2272 ; 1824 % 32 == 0
#define OFF_H     2288      // 448 -> 2736 ; 2288 % 32 == 16 (disjoint banks vs sX)
#define OFF_H2    2736      // 7*80 = 560 -> 3296 (quarter-padded copy for heads)
#define OFF_C     3296      // 448 -> 3744
#define OFF_GATE  3744      // 7*256 = 1792 -> 5536
#define SM_TOT    5536      // 22144 bytes

#define OFFZ ((size_t)B_ * T_ * 18)
#define OFFH ((size_t)B_ * T_ * 50)
#define OFFC (OFFH + (size_t)B_ * 64)

__device__ __forceinline__ float sigm(float x) {
    return 1.0f / (1.0f + __expf(-x));
}

__global__ __launch_bounds__(NTH, 1)
void wm_lstm_kernel(const float* __restrict__ obs, const float* __restrict__ act,
                    const float* __restrict__ h0,  const float* __restrict__ c0,
                    const float* __restrict__ Wenc, const float* __restrict__ benc,
                    const float* __restrict__ Wih,  const float* __restrict__ Whh,
                    const float* __restrict__ bih,  const float* __restrict__ bhh,
                    const float* __restrict__ Wpred, const float* __restrict__ bpred,
                    const float* __restrict__ Wz,    const float* __restrict__ bz,
                    float* __restrict__ out) {
    __shared__ float sm[SM_TOT];

    const int tid   = threadIdx.x;
    const int bBase = blockIdx.x * NBR;

    // ---- stage encoder weights (k-major) ----
    for (int idx = tid; idx < 23 * 64; idx += NTH) {
        int k = idx >> 6, j = idx & 63;
        sm[OFF_WENCT + idx] = Wenc[j * 23 + k];
    }
    if (tid < NBR * 64) {
        int nb = tid >> 6, j = tid & 63;
        int b = bBase + nb;
        float hv = 0.f, cv = 0.f;
        if (b < B_) { hv = h0[(size_t)b * 64 + j]; cv = c0[(size_t)b * 64 + j]; }
        sm[OFF_H + nb * 64 + j] = hv;
        sm[OFF_H2 + nb * 80 + (j >> 4) * 20 + (j & 15)] = hv;
        sm[OFF_C + nb * 64 + j] = cv;
    }

    // ---- gate setup (validated R6 scheme): lane pair per gate, w in regs ----
    const int  role = tid & 1;          // 0: W_ih (reads sX), 1: W_hh (reads sH)
    const int  g    = tid >> 1;         // 0..255
    float4 wreg[16];
    {
        const float* wsrc = (role ? Whh : Wih) + g * 64;
#pragma unroll
        for (int k4 = 0; k4 < 16; k4++)
            wreg[k4] = *(const float4*)(wsrc + k4 * 4);
    }
    const float bg = bih[g] + bhh[g];

    // ---- head setup: thread = (o, quarter), 224 threads = 7 full warps ----
    const int  ho = tid >> 2;           // 0..55 (active < 50)
    const int  hq = tid & 3;
    const bool headThr = (tid < 224);
    float4 hw0 = {0,0,0,0}, hw1 = {0,0,0,0}, hw2 = {0,0,0,0}, hw3 = {0,0,0,0};
    float bh = 0.f;
    if (headThr && ho < 50) {
        const float* src = ((ho < 18) ? Wpred + ho * 64 : Wz + (ho - 18) * 64) + hq * 16;
        hw0 = *(const float4*)(src);
        hw1 = *(const float4*)(src + 4);
        hw2 = *(const float4*)(src + 8);
        hw3 = *(const float4*)(src + 12);
        bh  = (ho < 18) ? bpred[ho] : bz[ho - 18];
    }

    // ---- encoder constants ----
    const int  enb = tid >> 6, ej = tid & 63;     // tid < 448
    const float be = benc[ej];

    // ---- input prefetch: 161 scalars per step, double-buffered sIn ----
    const int  pNb = tid / 23;
    const int  pK  = tid - pNb * 23;
    const int  pb  = bBase + pNb;
    const bool pValid = (tid < NBR * 23) && (pb < B_);
    const float* pPtr = nullptr;
    int pStep = 0;
    if (pValid) {
        if (pK < 18) { pPtr = obs + ((size_t)pb * T_) * 18 + pK;       pStep = 18; }
        else         { pPtr = act + ((size_t)pb * T_) * 5 + (pK - 18); pStep = 5;  }
    }
    float rIn = pValid ? pPtr[0] : 0.f;                 // in(0)
    if (tid < NBR * 23) sm[OFF_IN + pNb * 24 + pK] = rIn;   // commit t=0 -> buf0
    rIn = pValid ? __ldg(pPtr + pStep) : 0.f;               // in(1)

    __syncthreads();

    for (int t = 0; t <= T_; t++) {
        // ---- P1: heads(t-1)  ||  enc(t) + input commit/prefetch ----
        if (t > 0 && headThr) {
#pragma unroll
            for (int nb = 0; nb < NBR; nb++) {
                const float4* hp = (const float4*)(sm + OFF_H2 + nb * 80 + hq * 20);
                const float4 a0 = hp[0], a1 = hp[1], a2 = hp[2], a3 = hp[3];
                float s;
                s = hw0.x * a0.x;
                s = fmaf(hw0.y, a0.y, s); s = fmaf(hw0.z, a0.z, s); s = fmaf(hw0.w, a0.w, s);
                s = fmaf(hw1.x, a1.x, s); s = fmaf(hw1.y, a1.y, s);
                s = fmaf(hw1.z, a1.z, s); s = fmaf(hw1.w, a1.w, s);
                s = fmaf(hw2.x, a2.x, s); s = fmaf(hw2.y, a2.y, s);
                s = fmaf(hw2.z, a2.z, s); s = fmaf(hw2.w, a2.w, s);
                s = fmaf(hw3.x, a3.x, s); s = fmaf(hw3.y, a3.y, s);
                s = fmaf(hw3.z, a3.z, s); s = fmaf(hw3.w, a3.w, s);
                s += __shfl_xor_sync(0xffffffffu, s, 1);
                s += __shfl_xor_sync(0xffffffffu, s, 2);
                int b = bBase + nb;
                if (hq == 0 && ho < 50 && b < B_) {
                    float v = s + bh;
                    size_t row = (size_t)b * T_ + (t - 1);
                    if (ho < 18) out[row * 18 + ho] = sigm(v);
                    else         out[OFFZ + row * 32 + (ho - 18)] = v;
                }
            }
        }
        if (t == T_) break;

        if (t + 1 < T_ && tid < NBR * 23)
            sm[OFF_IN + ((t + 1) & 1) * 168 + pNb * 24 + pK] = rIn;   // commit in(t+1)
        {
            int tn = (t + 2 < T_) ? t + 2 : T_ - 1;
            if (pValid) rIn = __ldg(pPtr + (size_t)tn * pStep);        // prefetch
        }
        if (tid < NBR * 64) {   // encoder(t): reads sIn buf[t&1]
            const float4* ib = (const float4*)(sm + OFF_IN + (t & 1) * 168 + enb * 24);
            float a = be;
            float4 qv;
#define WK(k) sm[OFF_WENCT + (k) * 64 + ej]
            qv = ib[0];
            a = fmaf(WK(0), qv.x, a); a = fmaf(WK(1), qv.y, a);
            a = fmaf(WK(2), qv.z, a); a = fmaf(WK(3), qv.w, a);
            qv = ib[1];
            a = fmaf(WK(4), qv.x, a); a = fmaf(WK(5), qv.y, a);
            a = fmaf(WK(6), qv.z, a); a = fmaf(WK(7), qv.w, a);
            qv = ib[2];
            a = fmaf(WK(8), qv.x, a); a = fmaf(WK(9), qv.y, a);
            a = fmaf(WK(10), qv.z, a); a = fmaf(WK(11), qv.w, a);
            qv = ib[3];
            a = fmaf(WK(12), qv.x, a); a = fmaf(WK(13), qv.y, a);
            a = fmaf(WK(14), qv.z, a); a = fmaf(WK(15), qv.w, a);
            qv = ib[4];
            a = fmaf(WK(16), qv.x, a); a = fmaf(WK(17), qv.y, a);
            a = fmaf(WK(18), qv.z, a); a = fmaf(WK(19), qv.w, a);
            qv = ib[5];
            a = fmaf(WK(20), qv.x, a); a = fmaf(WK(21), qv.y, a);
            a = fmaf(WK(22), qv.z, a);
#undef WK
            sm[OFF_X + enb * 64 + ej] = fmaxf(a, 0.f);
        }
        __syncthreads();

        // ---- P2: gate GEMM (unchanged from R6) ----
        {
            const float* vbase = sm + (role ? OFF_H : OFF_X);
            float acc[NBR];
#pragma unroll
            for (int i = 0; i < NBR; i++) acc[i] = 0.f;
#pragma unroll
            for (int k4 = 0; k4 < 16; k4++) {
                const float4 w = wreg[k4];
#pragma unroll
                for (int nb = 0; nb < NBR; nb++) {
                    const float4 v = *(const float4*)(vbase + nb * 64 + k4 * 4);
                    acc[nb] = fmaf(w.x, v.x, acc[nb]);
                    acc[nb] = fmaf(w.y, v.y, acc[nb]);
                    acc[nb] = fmaf(w.z, v.z, acc[nb]);
                    acc[nb] = fmaf(w.w, v.w, acc[nb]);
                }
            }
#pragma unroll
            for (int nb = 0; nb < NBR; nb++) {
                float s = acc[nb];
                s += __shfl_xor_sync(0xffffffffu, s, 1);
                if (!role) sm[OFF_GATE + nb * 256 + g] = s + bg;
            }
        }
        __syncthreads();

        // ---- P3: LSTM cell elementwise, dual-store h ----
        if (tid < NBR * 64) {
            const float* gr = sm + OFF_GATE + enb * 256;
            float gi = gr[ej], gf = gr[64 + ej], gg = gr[128 + ej], go = gr[192 + ej];
            float cc = sm[OFF_C + enb * 64 + ej];
            cc = sigm(gf) * cc + sigm(gi) * tanhf(gg);
            float hh = sigm(go) * tanhf(cc);
            sm[OFF_C + enb * 64 + ej] = cc;
            sm[OFF_H + enb * 64 + ej] = hh;
            sm[OFF_H2 + enb * 80 + (ej >> 4) * 20 + (ej & 15)] = hh;
        }
        __syncthreads();
    }

    // ---- final hT / cT (sH/sC unchanged since last P3 sync) ----
    if (tid < NBR * 64) {
        int b = bBase + enb;
        if (b < B_) {
            out[OFFH + (size_t)b * 64 + ej] = sm[OFF_H + enb * 64 + ej];
            out[OFFC + (size_t)b * 64 + ej] = sm[OFF_C + enb * 64 + ej];
        }
    }
}

extern "C" void kernel_launch(void* const* d_in, const int* in_sizes, int n_in,
                              void* d_out, int out_size) {
    (void)in_sizes; (void)n_in; (void)out_size;
    wm_lstm_kernel<<<NBLK, NTH>>>(
        (const float*)d_in[0],  (const float*)d_in[1],
        (const float*)d_in[2],  (const float*)d_in[3],
        (const float*)d_in[4],  (const float*)d_in[5],
        (const float*)d_in[6],  (const float*)d_in[7],
        (const float*)d_in[8],  (const float*)d_in[9],
        (const float*)d_in[10], (const float*)d_in[11],
        (const float*)d_in[12], (const float*)d_in[13],
        (float*)d_out);
}

// round 15
// speedup vs baseline: 2.1959x; 1.2547x over previous
#include <cuda_runtime.h>

#define B_   1024
#define T_   1024
#define NBR  7
#define NTH  512
#define NBLK 147        // 147*7 = 1029 >= 1024

// ---- shared memory layout (float offsets) ----
#define OFF_WHEAD 0         // 50*68 = 3400
#define OFF_WENCT 3400      // 23*64 = 1472 -> 4872  [k][j]
#define OFF_IN    4880      // 2 bufs * 168 = 336 -> 5216
#define OFF_X0    5248      // 448 -> 5696 ; 5248 % 32 == 0
#define OFF_X1    5696      // 448 -> 6144 ; % 32 == 0
#define OFF_H     6160      // 448 -> 6608 ; % 32 == 16 (banks disjoint from sX)
#define OFF_C     6608      // 448 -> 7056
#define OFF_GATE  7056      // 1792 -> 8848
#define SM_TOT    8848      // 35392 bytes

#define OFFZ ((size_t)B_ * T_ * 18)
#define OFFH ((size_t)B_ * T_ * 50)
#define OFFC (OFFH + (size_t)B_ * 64)

__device__ __forceinline__ float sigm(float x) {
    return 1.0f / (1.0f + __expf(-x));
}

__global__ __launch_bounds__(NTH, 1)
void wm_lstm_kernel(const float* __restrict__ obs, const float* __restrict__ act,
                    const float* __restrict__ h0,  const float* __restrict__ c0,
                    const float* __restrict__ Wenc, const float* __restrict__ benc,
                    const float* __restrict__ Wih,  const float* __restrict__ Whh,
                    const float* __restrict__ bih,  const float* __restrict__ bhh,
                    const float* __restrict__ Wpred, const float* __restrict__ bpred,
                    const float* __restrict__ Wz,    const float* __restrict__ bz,
                    float* __restrict__ out) {
    __shared__ float sm[SM_TOT];

    const int tid   = threadIdx.x;
    const int bBase = blockIdx.x * NBR;

    // ---- stage head/encoder weights into shared ----
    for (int idx = tid; idx < 50 * 64; idx += NTH) {
        int o = idx >> 6, k = idx & 63;
        sm[OFF_WHEAD + o * 68 + k] = (o < 18) ? Wpred[o * 64 + k] : Wz[(o - 18) * 64 + k];
    }
    for (int idx = tid; idx < 23 * 64; idx += NTH) {
        int k = idx >> 6, j = idx & 63;
        sm[OFF_WENCT + idx] = Wenc[j * 23 + k];   // transposed [k][j]
    }
    if (tid < NBR * 64) {
        int nb = tid >> 6, j = tid & 63;
        int b = bBase + nb;
        float hv = 0.f, cv = 0.f;
        if (b < B_) { hv = h0[(size_t)b * 64 + j]; cv = c0[(size_t)b * 64 + j]; }
        sm[OFF_H + tid] = hv;
        sm[OFF_C + tid] = cv;
    }

    // ---- gate setup (R6-validated): lane pair per gate, weights in regs ----
    const int  role = tid & 1;          // 0: W_ih (reads sX), 1: W_hh (reads sH)
    const int  g    = tid >> 1;         // 0..255
    float4 wreg[16];
    {
        const float* wsrc = (role ? Whh : Wih) + g * 64;
#pragma unroll
        for (int k4 = 0; k4 < 16; k4++)
            wreg[k4] = *(const float4*)(wsrc + k4 * 4);
    }
    const float bg = bih[g] + bhh[g];

    // ---- head constants: one thread per (nb, o), tid < 350 ----
    const bool headThr = (tid < NBR * 50);
    const int  hNb = tid / 50;
    const int  hO  = tid - hNb * 50;
    const int  hB  = bBase + hNb;
    const float bh = headThr ? ((hO < 18) ? bpred[hO] : bz[hO - 18]) : 0.f;

    // ---- in-loop encoder constants: tid >= 384, fixed column j ----
    const bool encThr = (tid >= 384);
    const int  e0 = tid - 384;              // 0..127
    const int  ej = e0 & 63;
    const int  enb0 = e0 >> 6;              // 0 or 1
    const int  encCnt = (e0 < 64) ? 4 : 3;  // uniform per warp
    const float beR = benc[ej];

    // ---- input prefetch: 161 scalars/step, double-buffered sIn ----
    const int  pNb = tid / 23;
    const int  pK  = tid - pNb * 23;
    const int  pb  = bBase + pNb;
    const bool pValid = (tid < NBR * 23) && (pb < B_);
    const float* pPtr = nullptr;
    int pStep = 0;
    if (pValid) {
        if (pK < 18) { pPtr = obs + ((size_t)pb * T_) * 18 + pK;       pStep = 18; }
        else         { pPtr = act + ((size_t)pb * T_) * 5 + (pK - 18); pStep = 5;  }
    }
    // prologue input pipeline: commit in(0)->buf0, in(1)->buf1, hold in(2)
    float rIn = pValid ? pPtr[0] : 0.f;
    if (tid < NBR * 23) sm[OFF_IN + pNb * 24 + pK] = rIn;
    if (pValid) rIn = __ldg(pPtr + pStep);
    if (tid < NBR * 23) sm[OFF_IN + 168 + pNb * 24 + pK] = rIn;
    if (pValid) rIn = __ldg(pPtr + 2 * pStep);

    __syncthreads();

    // prologue: enc(0) -> sX0 (one output per thread, tid < 448)
    if (tid < NBR * 64) {
        int nb = tid >> 6, j = tid & 63;
        float a = benc[j];
#pragma unroll
        for (int k = 0; k < 23; k++)
            a = fmaf(sm[OFF_WENCT + k * 64 + j], sm[OFF_IN + nb * 24 + k], a);
        sm[OFF_X0 + nb * 64 + j] = fmaxf(a, 0.f);
    }
    __syncthreads();

    for (int t = 0; t < T_; t++) {
        // ======== MEGA phase ========
        // (i) commit in(t+2) -> sIn buf[t&1]
        if (tid < NBR * 23)
            sm[OFF_IN + (t & 1) * 168 + pNb * 24 + pK] = rIn;

        // (ii) gates(t): read sX[t&1] (role 0) / sH (role 1)
        {
            const float* vbase = role ? (sm + OFF_H)
                                      : (sm + ((t & 1) ? OFF_X1 : OFF_X0));
            float acc[NBR];
#pragma unroll
            for (int i = 0; i < NBR; i++) acc[i] = 0.f;
#pragma unroll
            for (int k4 = 0; k4 < 16; k4++) {
                const float4 w = wreg[k4];
#pragma unroll
                for (int nb = 0; nb < NBR; nb++) {
                    const float4 v = *(const float4*)(vbase + nb * 64 + k4 * 4);
                    acc[nb] = fmaf(w.x, v.x, acc[nb]);
                    acc[nb] = fmaf(w.y, v.y, acc[nb]);
                    acc[nb] = fmaf(w.z, v.z, acc[nb]);
                    acc[nb] = fmaf(w.w, v.w, acc[nb]);
                }
            }
#pragma unroll
            for (int nb = 0; nb < NBR; nb++) {
                float s = acc[nb];
                s += __shfl_xor_sync(0xffffffffu, s, 1);
                if (!role) sm[OFF_GATE + nb * 256 + g] = s + bg;
            }
        }

        // (iii) heads(t-1): reads sH = h(t-1), same value gates just read
        if (t > 0 && headThr) {
            float a = bh;
            const float* wr = sm + OFF_WHEAD + hO * 68;
            const float* hr = sm + OFF_H + hNb * 64;
#pragma unroll
            for (int k4 = 0; k4 < 16; k4++) {
                const float4 w = *(const float4*)(wr + k4 * 4);
                const float4 h = *(const float4*)(hr + k4 * 4);
                a = fmaf(w.x, h.x, a);
                a = fmaf(w.y, h.y, a);
                a = fmaf(w.z, h.z, a);
                a = fmaf(w.w, h.w, a);
            }
            if (hB < B_) {
                size_t row = (size_t)hB * T_ + (t - 1);
                if (hO < 18) out[row * 18 + hO] = sigm(a);
                else         out[OFFZ + row * 32 + (hO - 18)] = a;
            }
        }

        // (iv) enc(t+1): reads sIn buf[(t+1)&1], writes sX[(t+1)&1]
        if (encThr && (t + 1 < T_)) {
            float wv[23];
#pragma unroll
            for (int k = 0; k < 23; k++)
                wv[k] = sm[OFF_WENCT + k * 64 + ej];
            const float* inb = sm + OFF_IN + ((t + 1) & 1) * 168;
            float* xw = sm + (((t + 1) & 1) ? OFF_X1 : OFF_X0);
#pragma unroll
            for (int i = 0; i < 4; i++) {
                if (i >= encCnt) break;
                int nb = (i < 3) ? (enb0 + i * 2) : 6;
                float a = beR;
#pragma unroll
                for (int k = 0; k < 23; k++)
                    a = fmaf(wv[k], inb[nb * 24 + k], a);
                xw[nb * 64 + ej] = fmaxf(a, 0.f);
            }
        }

        // (v) prefetch in(t+3)
        {
            int tn = (t + 3 < T_) ? (t + 3) : (T_ - 1);
            if (pValid) rIn = __ldg(pPtr + (size_t)tn * pStep);
        }
        __syncthreads();

        // ======== CELL phase ========
        if (tid < NBR * 64) {
            int nb = tid >> 6, j = tid & 63;
            const float* gr = sm + OFF_GATE + nb * 256;
            float gi = gr[j], gf = gr[64 + j], gg = gr[128 + j], go = gr[192 + j];
            float cc = sm[OFF_C + nb * 64 + j];
            cc = sigm(gf) * cc + sigm(gi) * tanhf(gg);
            float hh = sigm(go) * tanhf(cc);
            sm[OFF_C + nb * 64 + j] = cc;
            sm[OFF_H + nb * 64 + j] = hh;
        }
        __syncthreads();
    }

    // ---- epilogue: heads(T-1) + final hT / cT ----
    if (headThr) {
        float a = bh;
        const float* wr = sm + OFF_WHEAD + hO * 68;
        const float* hr = sm + OFF_H + hNb * 64;
#pragma unroll
        for (int k4 = 0; k4 < 16; k4++) {
            const float4 w = *(const float4*)(wr + k4 * 4);
            const float4 h = *(const float4*)(hr + k4 * 4);
            a = fmaf(w.x, h.x, a);
            a = fmaf(w.y, h.y, a);
            a = fmaf(w.z, h.z, a);
            a = fmaf(w.w, h.w, a);
        }
        if (hB < B_) {
            size_t row = (size_t)hB * T_ + (T_ - 1);
            if (hO < 18) out[row * 18 + hO] = sigm(a);
            else         out[OFFZ + row * 32 + (hO - 18)] = a;
        }
    }
    if (tid < NBR * 64) {
        int nb = tid >> 6, j = tid & 63;
        int b = bBase + nb;
        if (b < B_) {
            out[OFFH + (size_t)b * 64 + j] = sm[OFF_H + nb * 64 + j];
            out[OFFC + (size_t)b * 64 + j] = sm[OFF_C + nb * 64 + j];
        }
    }
}

extern "C" void kernel_launch(void* const* d_in, const int* in_sizes, int n_in,
                              void* d_out, int out_size) {
    (void)in_sizes; (void)n_in; (void)out_size;
    wm_lstm_kernel<<<NBLK, NTH>>>(
        (const float*)d_in[0],  (const float*)d_in[1],
        (const float*)d_in[2],  (const float*)d_in[3],
        (const float*)d_in[4],  (const float*)d_in[5],
        (const float*)d_in[6],  (const float*)d_in[7],
        (const float*)d_in[8],  (const float*)d_in[9],
        (const float*)d_in[10], (const float*)d_in[11],
        (const float*)d_in[12], (const float*)d_in[13],
        (float*)d_out);
}

// round 16
// speedup vs baseline: 2.2398x; 1.0200x over previous
#include <cuda_runtime.h>

#define B_   1024
#define T_   1024
#define NBR  7
#define NTH  512
#define NBLK 147        // 147*7 = 1029 >= 1024

// ---- shared memory layout (float offsets) ----
#define OFF_WHEAD 0         // 50*68 = 3400
#define OFF_WENCT 3400      // 23*64 = 1472 -> 4872  [k][j]
#define OFF_IN    4880      // 2 bufs * 168 = 336 -> 5216
#define OFF_X0    5248      // 448 -> 5696 ; 5248 % 32 == 0
#define OFF_X1    5696      // 448 -> 6144 ; % 32 == 0
#define OFF_H     6160      // 448 -> 6608 ; % 32 == 16 (banks disjoint from sX)
#define OFF_C     6608      // 448 -> 7056
#define OFF_GATE  7056      // 1792 -> 8848
#define SM_TOT    8848      // 35392 bytes

#define OFFZ ((size_t)B_ * T_ * 18)
#define OFFH ((size_t)B_ * T_ * 50)
#define OFFC (OFFH + (size_t)B_ * 64)

typedef unsigned long long ull;

__device__ __forceinline__ void fma2(ull& d, ull a, ull b) {
    asm("fma.rn.f32x2 %0, %1, %2, %0;" : "+l"(d) : "l"(a), "l"(b));
}
__device__ __forceinline__ float2 unpack2(ull v) {
    float2 r; asm("mov.b64 {%0,%1}, %2;" : "=f"(r.x), "=f"(r.y) : "l"(v)); return r;
}
__device__ __forceinline__ float sigm(float x) {
    return 1.0f / (1.0f + __expf(-x));
}

__global__ __launch_bounds__(NTH, 1)
void wm_lstm_kernel(const float* __restrict__ obs, const float* __restrict__ act,
                    const float* __restrict__ h0,  const float* __restrict__ c0,
                    const float* __restrict__ Wenc, const float* __restrict__ benc,
                    const float* __restrict__ Wih,  const float* __restrict__ Whh,
                    const float* __restrict__ bih,  const float* __restrict__ bhh,
                    const float* __restrict__ Wpred, const float* __restrict__ bpred,
                    const float* __restrict__ Wz,    const float* __restrict__ bz,
                    float* __restrict__ out) {
    __shared__ float sm[SM_TOT];

    const int tid   = threadIdx.x;
    const int bBase = blockIdx.x * NBR;

    // ---- stage head/encoder weights into shared ----
    for (int idx = tid; idx < 50 * 64; idx += NTH) {
        int o = idx >> 6, k = idx & 63;
        sm[OFF_WHEAD + o * 68 + k] = (o < 18) ? Wpred[o * 64 + k] : Wz[(o - 18) * 64 + k];
    }
    for (int idx = tid; idx < 23 * 64; idx += NTH) {
        int k = idx >> 6, j = idx & 63;
        sm[OFF_WENCT + idx] = Wenc[j * 23 + k];   // transposed [k][j]
    }
    if (tid < NBR * 64) {
        int nb = tid >> 6, j = tid & 63;
        int b = bBase + nb;
        float hv = 0.f, cv = 0.f;
        if (b < B_) { hv = h0[(size_t)b * 64 + j]; cv = c0[(size_t)b * 64 + j]; }
        sm[OFF_H + tid] = hv;
        sm[OFF_C + tid] = cv;
    }

    // ---- gate setup: lane pair per gate, weights in regs as f32x2 pairs ----
    const int  role = tid & 1;          // 0: W_ih (reads sX), 1: W_hh (reads sH)
    const int  g    = tid >> 1;         // 0..255
    ull wreg2[32];                      // 64 weight floats as 32 packed pairs
    {
        const float* wsrc = (role ? Whh : Wih) + g * 64;
#pragma unroll
        for (int k4 = 0; k4 < 16; k4++) {
            ulonglong2 tq = *(const ulonglong2*)(wsrc + k4 * 4);
            wreg2[2 * k4]     = tq.x;   // floats 4k4, 4k4+1
            wreg2[2 * k4 + 1] = tq.y;   // floats 4k4+2, 4k4+3
        }
    }
    const float bg = bih[g] + bhh[g];

    // ---- head constants: one thread per (nb, o), tid < 350 ----
    const bool headThr = (tid < NBR * 50);
    const int  hNb = tid / 50;
    const int  hO  = tid - hNb * 50;
    const int  hB  = bBase + hNb;
    const float bh = headThr ? ((hO < 18) ? bpred[hO] : bz[hO - 18]) : 0.f;

    // ---- in-loop encoder constants: tid >= 384, fixed column j ----
    const bool encThr = (tid >= 384);
    const int  e0 = tid - 384;              // 0..127
    const int  ej = e0 & 63;
    const int  enb0 = e0 >> 6;              // 0 or 1
    const int  encCnt = (e0 < 64) ? 4 : 3;  // uniform per warp
    const float beR = benc[ej];

    // ---- input prefetch: 161 scalars/step, double-buffered sIn ----
    const int  pNb = tid / 23;
    const int  pK  = tid - pNb * 23;
    const int  pb  = bBase + pNb;
    const bool pValid = (tid < NBR * 23) && (pb < B_);
    const float* pPtr = nullptr;
    int pStep = 0;
    if (pValid) {
        if (pK < 18) { pPtr = obs + ((size_t)pb * T_) * 18 + pK;       pStep = 18; }
        else         { pPtr = act + ((size_t)pb * T_) * 5 + (pK - 18); pStep = 5;  }
    }
    // prologue input pipeline: commit in(0)->buf0, in(1)->buf1, hold in(2)
    float rIn = pValid ? pPtr[0] : 0.f;
    if (tid < NBR * 23) sm[OFF_IN + pNb * 24 + pK] = rIn;
    if (pValid) rIn = __ldg(pPtr + pStep);
    if (tid < NBR * 23) sm[OFF_IN + 168 + pNb * 24 + pK] = rIn;
    if (pValid) rIn = __ldg(pPtr + 2 * pStep);

    __syncthreads();

    // prologue: enc(0) -> sX0 (one output per thread, tid < 448)
    if (tid < NBR * 64) {
        int nb = tid >> 6, j = tid & 63;
        float a = benc[j];
#pragma unroll
        for (int k = 0; k < 23; k++)
            a = fmaf(sm[OFF_WENCT + k * 64 + j], sm[OFF_IN + nb * 24 + k], a);
        sm[OFF_X0 + nb * 64 + j] = fmaxf(a, 0.f);
    }
    __syncthreads();

    for (int t = 0; t < T_; t++) {
        // ======== MEGA phase ========
        // (i) commit in(t+2) -> sIn buf[t&1]
        if (tid < NBR * 23)
            sm[OFF_IN + (t & 1) * 168 + pNb * 24 + pK] = rIn;

        // (ii) gates(t): f32x2 packed; read sX[t&1] (role 0) / sH (role 1)
        {
            const float* vbase = role ? (sm + OFF_H)
                                      : (sm + ((t & 1) ? OFF_X1 : OFF_X0));
            ull acc[NBR];
#pragma unroll
            for (int i = 0; i < NBR; i++) acc[i] = 0ull;
#pragma unroll
            for (int k4 = 0; k4 < 16; k4++) {
                const ull w0 = wreg2[2 * k4];
                const ull w1 = wreg2[2 * k4 + 1];
#pragma unroll
                for (int nb = 0; nb < NBR; nb++) {
                    const ulonglong2 v = *(const ulonglong2*)(vbase + nb * 64 + k4 * 4);
                    fma2(acc[nb], w0, v.x);
                    fma2(acc[nb], w1, v.y);
                }
            }
#pragma unroll
            for (int nb = 0; nb < NBR; nb++) {
                float2 p = unpack2(acc[nb]);
                float s = p.x + p.y;
                s += __shfl_xor_sync(0xffffffffu, s, 1);
                if (!role) sm[OFF_GATE + nb * 256 + g] = s + bg;
            }
        }

        // (iii) heads(t-1): f32x2, dense stride (4 floats per 16B load)
        if (t > 0 && headThr) {
            ull a2 = 0ull;
            const float* wr = sm + OFF_WHEAD + hO * 68;
            const float* hr = sm + OFF_H + hNb * 64;
#pragma unroll
            for (int k4 = 0; k4 < 16; k4++) {
                const ulonglong2 w = *(const ulonglong2*)(wr + k4 * 4);
                const ulonglong2 h = *(const ulonglong2*)(hr + k4 * 4);
                fma2(a2, w.x, h.x);
                fma2(a2, w.y, h.y);
            }
            float2 p = unpack2(a2);
            float a = bh + p.x + p.y;
            if (hB < B_) {
                size_t row = (size_t)hB * T_ + (t - 1);
                if (hO < 18) out[row * 18 + hO] = sigm(a);
                else         out[OFFZ + row * 32 + (hO - 18)] = a;
            }
        }

        // (iv) enc(t+1): reads sIn buf[(t+1)&1], writes sX[(t+1)&1]
        if (encThr && (t + 1 < T_)) {
            float wv[23];
#pragma unroll
            for (int k = 0; k < 23; k++)
                wv[k] = sm[OFF_WENCT + k * 64 + ej];
            const float* inb = sm + OFF_IN + ((t + 1) & 1) * 168;
            float* xw = sm + (((t + 1) & 1) ? OFF_X1 : OFF_X0);
#pragma unroll
            for (int i = 0; i < 4; i++) {
                if (i >= encCnt) break;
                int nb = (i < 3) ? (enb0 + i * 2) : 6;
                float a = beR;
#pragma unroll
                for (int k = 0; k < 23; k++)
                    a = fmaf(wv[k], inb[nb * 24 + k], a);
                xw[nb * 64 + ej] = fmaxf(a, 0.f);
            }
        }

        // (v) prefetch in(t+3)
        {
            int tn = (t + 3 < T_) ? (t + 3) : (T_ - 1);
            if (pValid) rIn = __ldg(pPtr + (size_t)tn * pStep);
        }
        __syncthreads();

        // ======== CELL phase ========
        if (tid < NBR * 64) {
            int nb = tid >> 6, j = tid & 63;
            const float* gr = sm + OFF_GATE + nb * 256;
            float gi = gr[j], gf = gr[64 + j], gg = gr[128 + j], go = gr[192 + j];
            float cc = sm[OFF_C + nb * 64 + j];
            cc = sigm(gf) * cc + sigm(gi) * tanhf(gg);
            float hh = sigm(go) * tanhf(cc);
            sm[OFF_C + nb * 64 + j] = cc;
            sm[OFF_H + nb * 64 + j] = hh;
        }
        __syncthreads();
    }

    // ---- epilogue: heads(T-1) + final hT / cT ----
    if (headThr) {
        ull a2 = 0ull;
        const float* wr = sm + OFF_WHEAD + hO * 68;
        const float* hr = sm + OFF_H + hNb * 64;
#pragma unroll
        for (int k4 = 0; k4 < 16; k4++) {
            const ulonglong2 w = *(const ulonglong2*)(wr + k4 * 4);
            const ulonglong2 h = *(const ulonglong2*)(hr + k4 * 4);
            fma2(a2, w.x, h.x);
            fma2(a2, w.y, h.y);
        }
        float2 p = unpack2(a2);
        float a = bh + p.x + p.y;
        if (hB < B_) {
            size_t row = (size_t)hB * T_ + (T_ - 1);
            if (hO < 18) out[row * 18 + hO] = sigm(a);
            else         out[OFFZ + row * 32 + (hO - 18)] = a;
        }
    }
    if (tid < NBR * 64) {
        int nb = tid >> 6, j = tid & 63;
        int b = bBase + nb;
        if (b < B_) {
            out[OFFH + (size_t)b * 64 + j] = sm[OFF_H + nb * 64 + j];
            out[OFFC + (size_t)b * 64 + j] = sm[OFF_C + nb * 64 + j];
        }
    }
}

extern "C" void kernel_launch(void* const* d_in, const int* in_sizes, int n_in,
                              void* d_out, int out_size) {
    (void)in_sizes; (void)n_in; (void)out_size;
    wm_lstm_kernel<<<NBLK, NTH>>>(
        (const float*)d_in[0],  (const float*)d_in[1],
        (const float*)d_in[2],  (const float*)d_in[3],
        (const float*)d_in[4],  (const float*)d_in[5],
        (const float*)d_in[6],  (const float*)d_in[7],
        (const float*)d_in[8],  (const float*)d_in[9],
        (const float*)d_in[10], (const float*)d_in[11],
        (const float*)d_in[12], (const float*)d_in[13],
        (float*)d_out);
}